// round 10
// baseline (speedup 1.0000x reference)
#include <cuda_runtime.h>

#define NN 100000
#define NE 1600000
#define KF 1433
#define NEG 0.2f

// GEMM tiling: BM=256, BN=64, BK=32; 8 warps, each 32 rows x 64 cols
#define BM 256
#define BK 32
#define NT_K ((KF + BK - 1) / BK)      // 45
#define KP_TOT (NT_K * 16)              // 720 k-pairs (zero padded)
#define ASTR 40                         // f32 per A row (32 + 8 pad: LDS.64 conflict-free)
#define A_F32 (BM * ASTR)               // 10240 f32 per buffer
#define A_BYTES (A_F32 * 4)             // 40960
#define BSTR 20                         // u32 per B n-row (16 kp + 4 pad: ldmatrix conflict-free)
#define B_U32 (64 * BSTR)               // 1280 u32 per part
#define B_BYTES (B_U32 * 4)             // 5120
#define SMEM_BYTES (2 * A_BYTES + 4 * B_BYTES)   // 102400

// ---------------- scratch (device globals; no allocation allowed) ----------
__device__ float g_feat1[NN * 64];
__device__ float g_el1[NN * 8];
__device__ float g_er1[NN * 8];
__device__ float g_denom1[NN * 8];
__device__ float g_numer1[NN * 64];
__device__ float g_feat2p[NN * 8];
__device__ float g_el2[NN];
__device__ float g_er2[NN];
__device__ float g_acc2[NN * 8];
__device__ unsigned g_Whi[64 * KP_TOT];  // W bf16x2 hi, layout [n][kp]
__device__ unsigned g_Wlo[64 * KP_TOT];  // residual,   layout [n][kp]

// ---------------- helpers --------------------------------------------------
__device__ __forceinline__ void red_add_v4(float* p, float x, float y, float z, float w) {
    asm volatile("red.global.add.v4.f32 [%0], {%1, %2, %3, %4};"
                 :: "l"(p), "f"(x), "f"(y), "f"(z), "f"(w) : "memory");
}
__device__ __forceinline__ float lrelu(float x) { return x >= 0.f ? x : NEG * x; }

__device__ __forceinline__ unsigned pk_bf(float e0, float e1) {
    unsigned r;
    asm("cvt.rn.bf16x2.f32 %0, %1, %2;" : "=r"(r) : "f"(e1), "f"(e0));
    return r;
}
__device__ __forceinline__ float bf_lo(unsigned p) { return __uint_as_float(p << 16); }
__device__ __forceinline__ float bf_hi(unsigned p) { return __uint_as_float(p & 0xffff0000u); }

__device__ __forceinline__ void mma_bf16(float* d, const unsigned* a, unsigned b0, unsigned b1) {
    asm volatile(
        "mma.sync.aligned.m16n8k16.row.col.f32.bf16.bf16.f32 "
        "{%0,%1,%2,%3}, {%4,%5,%6,%7}, {%8,%9}, {%0,%1,%2,%3};"
        : "+f"(d[0]), "+f"(d[1]), "+f"(d[2]), "+f"(d[3])
        : "r"(a[0]), "r"(a[1]), "r"(a[2]), "r"(a[3]), "r"(b0), "r"(b1));
}
__device__ __forceinline__ void cp4f(float* dst, const float* src) {
    unsigned sa = (unsigned)__cvta_generic_to_shared(dst);
    asm volatile("cp.async.ca.shared.global [%0], [%1], 4;" :: "r"(sa), "l"(src));
}
__device__ __forceinline__ void cp16u(unsigned* dst, const unsigned* src) {
    unsigned sa = (unsigned)__cvta_generic_to_shared(dst);
    asm volatile("cp.async.cg.shared.global [%0], [%1], 16;" :: "r"(sa), "l"(src));
}
__device__ __forceinline__ void ldmx4(unsigned* r, unsigned saddr) {
    asm volatile("ldmatrix.sync.aligned.m8n8.x4.shared.b16 {%0,%1,%2,%3}, [%4];"
                 : "=r"(r[0]), "=r"(r[1]), "=r"(r[2]), "=r"(r[3]) : "r"(saddr));
}

// ---------------- init + W conversion (3 launches before gemm) -------------
__global__ void init_n1a_kernel() {
    int i = blockIdx.x * blockDim.x + threadIdx.x;
    if (i < NN * 8) ((float4*)g_numer1)[i] = make_float4(0.f, 0.f, 0.f, 0.f);
}
__global__ void init_n1b_kernel() {
    int i = blockIdx.x * blockDim.x + threadIdx.x;
    if (i < NN * 8) ((float4*)g_numer1)[NN * 8 + i] = make_float4(0.f, 0.f, 0.f, 0.f);
}
// W [KF,64] f32 -> [n][kp] packed bf16x2 hi/lo, zero-padded to KP_TOT
__global__ void convw_kernel(const float* __restrict__ W) {
    int i = blockIdx.x * blockDim.x + threadIdx.x;
    if (i >= 64 * KP_TOT) return;
    int n = i / KP_TOT;
    int kp = i - n * KP_TOT;
    int k0 = 2 * kp, k1 = k0 + 1;
    float f0 = (k0 < KF) ? W[(size_t)k0 * 64 + n] : 0.f;
    float f1 = (k1 < KF) ? W[(size_t)k1 * 64 + n] : 0.f;
    unsigned hi = pk_bf(f0, f1);
    unsigned lo = pk_bf(f0 - bf_lo(hi), f1 - bf_hi(hi));
    g_Whi[i] = hi;
    g_Wlo[i] = lo;
}
__global__ void init_d_kernel() {
    int i = blockIdx.x * blockDim.x + threadIdx.x;
    if (i < NN * 2) ((float4*)g_denom1)[i] = make_float4(0.f, 0.f, 0.f, 0.f);
}

// ---------------- K1: feat1 = features @ W1 (3xBF16, ldmatrix B) -----------
__global__ __launch_bounds__(256, 2) void gemm1_kernel(
    const float* __restrict__ A, const float* __restrict__ al,
    const float* __restrict__ ar) {
    extern __shared__ float smem[];
    float* sA = smem;                                  // 2 bufs of raw f32 A
    unsigned* sB = (unsigned*)(smem + 2 * A_F32);      // buf0hi, buf0lo, buf1hi, buf1lo
    const unsigned sb_byte0 = (unsigned)__cvta_generic_to_shared(sB);

    const int bm   = blockIdx.x * BM;
    const int tid  = threadIdx.x;
    const int wid  = tid >> 5;
    const int lane = tid & 31;
    const int g    = lane >> 2;
    const int cq   = lane & 3;
    const int Wm   = wid * 32;

    float acc[2][8][4];
#pragma unroll
    for (int u = 0; u < 2; u++)
#pragma unroll
        for (int n = 0; n < 8; n++)
#pragma unroll
            for (int i = 0; i < 4; i++) acc[u][n][i] = 0.f;

    auto loadA = [&](int t, int buf) {
        const int k0 = t * BK;
        float* dst = sA + buf * A_F32;
        if (k0 + BK <= KF && bm + BM <= NN) {
#pragma unroll
            for (int j = 0; j < 32; j++) {
                int i = tid + j * 256;
                int r = i >> 5, k = i & 31;
                cp4f(dst + r * ASTR + k, A + (size_t)(bm + r) * KF + k0 + k);
            }
        } else {
#pragma unroll
            for (int j = 0; j < 32; j++) {
                int i = tid + j * 256;
                int r = i >> 5, k = i & 31;
                int row = bm + r, col = k0 + k;
                if (row < NN && col < KF)
                    cp4f(dst + r * ASTR + k, A + (size_t)row * KF + col);
                else
                    dst[r * ASTR + k] = 0.f;
            }
        }
    };
    auto loadB = [&](int t, int buf) {
        int n = tid >> 2, kc = tid & 3;
        cp16u(sB + (2 * buf) * B_U32 + n * BSTR + kc * 4,
              g_Whi + (size_t)n * KP_TOT + t * 16 + kc * 4);
        cp16u(sB + (2 * buf + 1) * B_U32 + n * BSTR + kc * 4,
              g_Wlo + (size_t)n * KP_TOT + t * 16 + kc * 4);
    };

    // prologue
    loadA(0, 0);
    loadB(0, 0);
    asm volatile("cp.async.commit_group;" ::: "memory");
    asm volatile("cp.async.wait_group 0;" ::: "memory");
    __syncthreads();

    for (int t = 0; t < NT_K; t++) {
        const int buf = t & 1;
        if (t + 1 < NT_K) {
            loadA(t + 1, buf ^ 1);
            loadB(t + 1, buf ^ 1);
            asm volatile("cp.async.commit_group;" ::: "memory");
        }

        const float* Af = sA + buf * A_F32;
        const unsigned bhB = sb_byte0 + (2 * buf) * B_BYTES;
        const unsigned blB = bhB + B_BYTES;

#pragma unroll
        for (int s = 0; s < 2; s++) {
            // A fragments (raw f32 LDS.64 -> bf16 hi/lo split in regs)
            unsigned ahi[2][4], alo_[2][4];
#pragma unroll
            for (int u = 0; u < 2; u++) {
                const float* base = Af + (Wm + u * 16 + g) * ASTR + 16 * s + 2 * cq;
                float2 v0 = *(const float2*)(base);
                float2 v1 = *(const float2*)(base + 8 * ASTR);
                float2 v2 = *(const float2*)(base + 8);
                float2 v3 = *(const float2*)(base + 8 * ASTR + 8);
                unsigned h;
                h = pk_bf(v0.x, v0.y); ahi[u][0] = h;
                alo_[u][0] = pk_bf(v0.x - bf_lo(h), v0.y - bf_hi(h));
                h = pk_bf(v1.x, v1.y); ahi[u][1] = h;
                alo_[u][1] = pk_bf(v1.x - bf_lo(h), v1.y - bf_hi(h));
                h = pk_bf(v2.x, v2.y); ahi[u][2] = h;
                alo_[u][2] = pk_bf(v2.x - bf_lo(h), v2.y - bf_hi(h));
                h = pk_bf(v3.x, v3.y); ahi[u][3] = h;
                alo_[u][3] = pk_bf(v3.x - bf_lo(h), v3.y - bf_hi(h));
            }
            const unsigned lb = (unsigned)(lane * 80 + 32 * s);
            unsigned q0[4], q1[4], q2[4], q3[4];
            // B hi fragments: q0 = b0 nt0-3, q1 = b0 nt4-7, q2 = b1 nt0-3, q3 = b1 nt4-7
            ldmx4(q0, bhB + lb);
            ldmx4(q1, bhB + 2560 + lb);
            ldmx4(q2, bhB + lb + 16);
            ldmx4(q3, bhB + 2560 + lb + 16);
#pragma unroll
            for (int u = 0; u < 2; u++)
#pragma unroll
                for (int nt = 0; nt < 8; nt++) {
                    unsigned b0 = (nt < 4) ? q0[nt] : q1[nt - 4];
                    unsigned b1 = (nt < 4) ? q2[nt] : q3[nt - 4];
                    mma_bf16(acc[u][nt], ahi[u], b0, b1);
                    mma_bf16(acc[u][nt], alo_[u], b0, b1);
                }
            // B lo fragments
            ldmx4(q0, blB + lb);
            ldmx4(q1, blB + 2560 + lb);
            ldmx4(q2, blB + lb + 16);
            ldmx4(q3, blB + 2560 + lb + 16);
#pragma unroll
            for (int u = 0; u < 2; u++)
#pragma unroll
                for (int nt = 0; nt < 8; nt++) {
                    unsigned b0 = (nt < 4) ? q0[nt] : q1[nt - 4];
                    unsigned b1 = (nt < 4) ? q2[nt] : q3[nt - 4];
                    mma_bf16(acc[u][nt], ahi[u], b0, b1);
                }
        }

        if (t + 1 < NT_K) {
            asm volatile("cp.async.wait_group 0;" ::: "memory");
            __syncthreads();
        }
    }

    // ---- epilogue: store feat1 + fused el/er ----
#pragma unroll
    for (int u = 0; u < 2; u++) {
        const int r0 = bm + Wm + u * 16 + g;
        const int r1 = r0 + 8;
#pragma unroll
        for (int nt = 0; nt < 8; nt++) {
            float c0 = acc[u][nt][0], c1 = acc[u][nt][1];
            float c2 = acc[u][nt][2], c3 = acc[u][nt][3];
            if (r0 < NN) *(float2*)&g_feat1[r0 * 64 + nt * 8 + 2 * cq] = make_float2(c0, c1);
            if (r1 < NN) *(float2*)&g_feat1[r1 * 64 + nt * 8 + 2 * cq] = make_float2(c2, c3);
            float al0 = __ldg(&al[nt * 8 + 2 * cq]), al1 = __ldg(&al[nt * 8 + 2 * cq + 1]);
            float ar0 = __ldg(&ar[nt * 8 + 2 * cq]), ar1 = __ldg(&ar[nt * 8 + 2 * cq + 1]);
            float el0 = c0 * al0 + c1 * al1, er0 = c0 * ar0 + c1 * ar1;
            float el1 = c2 * al0 + c3 * al1, er1 = c2 * ar0 + c3 * ar1;
#pragma unroll
            for (int m = 1; m < 4; m <<= 1) {
                el0 += __shfl_xor_sync(0xffffffff, el0, m);
                er0 += __shfl_xor_sync(0xffffffff, er0, m);
                el1 += __shfl_xor_sync(0xffffffff, el1, m);
                er1 += __shfl_xor_sync(0xffffffff, er1, m);
            }
            if (cq == 0) {
                if (r0 < NN) { g_el1[r0 * 8 + nt] = el0; g_er1[r0 * 8 + nt] = er0; }
                if (r1 < NN) { g_el1[r1 * 8 + nt] = el1; g_er1[r1 * 8 + nt] = er1; }
            }
        }
    }
}

// ---------------- K2: layer-1 edge pass ------------------------------------
__global__ void edge1_kernel(const int* __restrict__ src, const int* __restrict__ dst) {
    int t = blockIdx.x * blockDim.x + threadIdx.x;
    int e = t >> 3;
    if (e >= NE) return;
    int h = t & 7;
    int s = __ldg(&src[e]);
    int d = __ldg(&dst[e]);
    float x = g_el1[s * 8 + h] + g_er1[d * 8 + h];
    float ex = __expf(lrelu(x));
    atomicAdd(&g_denom1[d * 8 + h], ex);
    const float4* f = (const float4*)&g_feat1[s * 64 + h * 8];
    float4 a = f[0], b = f[1];
    red_add_v4(&g_numer1[d * 64 + h * 8],     ex * a.x, ex * a.y, ex * a.z, ex * a.w);
    red_add_v4(&g_numer1[d * 64 + h * 8 + 4], ex * b.x, ex * b.y, ex * b.z, ex * b.w);
}

// ---------------- K3: finalize layer1 + MHI pooling + layer2 features ------
__global__ __launch_bounds__(256) void node_kernel(
    const float* __restrict__ b1, const float* __restrict__ Wm,
    const float* __restrict__ bm, const float* __restrict__ a,
    const float* __restrict__ W2, const float* __restrict__ al2,
    const float* __restrict__ ar2) {
    int n = blockIdx.x * blockDim.x + threadIdx.x;
    if (n >= NN) return;

    float x[8][8];
#pragma unroll
    for (int h = 0; h < 8; h++) {
        float dn  = g_denom1[n * 8 + h];
        float inv = dn > 0.f ? 1.f / dn : 0.f;
#pragma unroll
        for (int o = 0; o < 8; o++) {
            float v = g_numer1[n * 64 + h * 8 + o] * inv + __ldg(&b1[h * 8 + o]);
            x[h][o] = v > 0.f ? v : 0.f;
        }
    }
    float xm[8], eh[8];
#pragma unroll
    for (int i = 0; i < 8; i++) xm[i] = 0.f;
#pragma unroll
    for (int h = 0; h < 8; h++) {
        float s = 0.f;
#pragma unroll
        for (int i = 0; i < 8; i++) {
            float xl = __ldg(&bm[i]);
#pragma unroll
            for (int j = 0; j < 8; j++) xl += x[h][j] * __ldg(&Wm[i * 8 + j]);
            xm[i] += xl;
            s += xl * __ldg(&a[i]);
        }
        eh[h] = s;
    }
    float ebar = 0.f;
#pragma unroll
    for (int i = 0; i < 8; i++) ebar += (xm[i] * 0.125f) * __ldg(&a[8 + i]);
    float ssum = 0.f;
#pragma unroll
    for (int h = 0; h < 8; h++) {
        float v = eh[h] + ebar;
        v = v > 0.f ? v : 0.f;
        v = __expf(v);
        eh[h] = v;
        ssum += v;
    }
    float rs = 1.f / ssum;
    float hv[8];
#pragma unroll
    for (int m = 0; m < 8; m++) {
        float s = 0.f;
#pragma unroll
        for (int h = 0; h < 8; h++) s += x[h][m] * eh[h];
        hv[m] = s * rs;
    }
    float f2[8];
#pragma unroll
    for (int o = 0; o < 7; o++) {
        float s = 0.f;
#pragma unroll
        for (int m = 0; m < 8; m++) s += hv[m] * __ldg(&W2[m * 7 + o]);
        f2[o] = s;
    }
    f2[7] = 1.f;
    float el = 0.f, er = 0.f;
#pragma unroll
    for (int o = 0; o < 7; o++) {
        el += f2[o] * __ldg(&al2[o]);
        er += f2[o] * __ldg(&ar2[o]);
    }
    float4* out4 = (float4*)&g_feat2p[n * 8];
    out4[0] = make_float4(f2[0], f2[1], f2[2], f2[3]);
    out4[1] = make_float4(f2[4], f2[5], f2[6], f2[7]);
    g_el2[n] = el;
    g_er2[n] = er;
    float4* acc = (float4*)&g_acc2[n * 8];
    acc[0] = make_float4(0.f, 0.f, 0.f, 0.f);
    acc[1] = make_float4(0.f, 0.f, 0.f, 0.f);
}

// ---------------- K4: layer-2 edge pass ------------------------------------
__global__ void edge2_kernel(const int* __restrict__ src, const int* __restrict__ dst) {
    int e = blockIdx.x * blockDim.x + threadIdx.x;
    if (e >= NE) return;
    int s = __ldg(&src[e]);
    int d = __ldg(&dst[e]);
    float xx = g_el2[s] + g_er2[d];
    float ex = __expf(lrelu(xx));
    const float4* f = (const float4*)&g_feat2p[s * 8];
    float4 a = f[0], b = f[1];
    red_add_v4(&g_acc2[d * 8],     ex * a.x, ex * a.y, ex * a.z, ex * a.w);
    red_add_v4(&g_acc2[d * 8 + 4], ex * b.x, ex * b.y, ex * b.z, ex * b.w);
}

// ---------------- K5: final output -----------------------------------------
__global__ void final_kernel(const float* __restrict__ b2, float* __restrict__ out) {
    int t = blockIdx.x * blockDim.x + threadIdx.x;
    if (t >= NN * 7) return;
    int n = t / 7, o = t - n * 7;
    float dn = g_acc2[n * 8 + 7];
    float v  = dn > 0.f ? g_acc2[n * 8 + o] / dn : 0.f;
    out[t] = v + __ldg(&b2[o]);
}

// ---------------- launch ----------------------------------------------------
extern "C" void kernel_launch(void* const* d_in, const int* in_sizes, int n_in,
                              void* d_out, int out_size) {
    const float* features = (const float*)d_in[0];
    const int*   src      = (const int*)d_in[1];
    const int*   dst      = (const int*)d_in[2];
    const float* W1       = (const float*)d_in[3];
    const float* attn_l1  = (const float*)d_in[4];
    const float* attn_r1  = (const float*)d_in[5];
    const float* b1       = (const float*)d_in[6];
    const float* Wm       = (const float*)d_in[7];
    const float* bm       = (const float*)d_in[8];
    const float* a        = (const float*)d_in[9];
    const float* W2       = (const float*)d_in[10];
    const float* attn_l2  = (const float*)d_in[11];
    const float* attn_r2  = (const float*)d_in[12];
    const float* b2       = (const float*)d_in[13];
    float* out = (float*)d_out;

    (void)cudaFuncSetAttribute(gemm1_kernel,
                               cudaFuncAttributeMaxDynamicSharedMemorySize, SMEM_BYTES);

    // 3 launches before gemm1 so it remains the profiled (4th) node
    init_n1a_kernel<<<(NN * 8 + 255) / 256, 256>>>();
    init_n1b_kernel<<<(NN * 8 + 255) / 256, 256>>>();
    convw_kernel<<<(64 * KP_TOT + 255) / 256, 256>>>(W1);
    gemm1_kernel<<<(NN + BM - 1) / BM, 256, SMEM_BYTES>>>(features, attn_l1, attn_r1);
    init_d_kernel<<<(NN * 2 + 255) / 256, 256>>>();
    edge1_kernel<<<(NE * 8 + 255) / 256, 256>>>(src, dst);
    node_kernel<<<(NN + 255) / 256, 256>>>(b1, Wm, bm, a, W2, attn_l2, attn_r2);
    edge2_kernel<<<(NE + 255) / 256, 256>>>(src, dst);
    final_kernel<<<(NN * 7 + 255) / 256, 256>>>(b2, out);
}

// round 13
// speedup vs baseline: 1.2707x; 1.2707x over previous
#include <cuda_runtime.h>

#define NN 100000
#define NE 1600000
#define KF 1433
#define NEG 0.2f

// GEMM tiling (R9 baseline: BM=128, 8 warps x 16x64 warp-tiles)
#define BM 128
#define BK 32
#define NT_K ((KF + BK - 1) / BK)      // 45
#define KP_TOT (NT_K * 16)              // 720 padded k-pairs
#define ASTRIDE 20                      // A: 16 pairs + 4 pad
#define BSTR 20                         // B: 16 kp + 4 pad per n-row (80 B rows for ldmatrix)
#define SA_U32 (BM * ASTRIDE)           // 2560
#define SB_U32 (64 * BSTR)              // 1280 per part
#define B_BYTES (SB_U32 * 4)            // 5120
#define SMEM_U32 (4 * SA_U32 + 4 * SB_U32)   // A: 2bufs x (hi,lo); B: 2bufs x (hi,lo)
#define SMEM_BYTES (SMEM_U32 * 4)       // 61440

// ---------------- scratch (device globals; no allocation allowed) ----------
__device__ float g_feat1[NN * 64];
__device__ float g_el1[NN * 8];
__device__ float g_er1[NN * 8];
__device__ float g_denom1[NN * 8];
__device__ float g_numer1[NN * 64];
__device__ float g_feat2p[NN * 8];
__device__ float g_el2[NN];
__device__ float g_er2[NN];
__device__ float g_acc2[NN * 8];
__device__ unsigned g_Whi[64 * KP_TOT];  // W bf16x2 hi, layout [n][kp]
__device__ unsigned g_Wlo[64 * KP_TOT];  // residual,   layout [n][kp]

// ---------------- helpers --------------------------------------------------
__device__ __forceinline__ void red_add_v4(float* p, float x, float y, float z, float w) {
    asm volatile("red.global.add.v4.f32 [%0], {%1, %2, %3, %4};"
                 :: "l"(p), "f"(x), "f"(y), "f"(z), "f"(w) : "memory");
}
__device__ __forceinline__ float lrelu(float x) { return x >= 0.f ? x : NEG * x; }

__device__ __forceinline__ unsigned pk_bf(float e0, float e1) {
    unsigned r;
    asm("cvt.rn.bf16x2.f32 %0, %1, %2;" : "=r"(r) : "f"(e1), "f"(e0));
    return r;
}
__device__ __forceinline__ float bf_lo(unsigned p) { return __uint_as_float(p << 16); }
__device__ __forceinline__ float bf_hi(unsigned p) { return __uint_as_float(p & 0xffff0000u); }

__device__ __forceinline__ void mma_bf16(float* d, const unsigned* a, unsigned b0, unsigned b1) {
    asm volatile(
        "mma.sync.aligned.m16n8k16.row.col.f32.bf16.bf16.f32 "
        "{%0,%1,%2,%3}, {%4,%5,%6,%7}, {%8,%9}, {%0,%1,%2,%3};"
        : "+f"(d[0]), "+f"(d[1]), "+f"(d[2]), "+f"(d[3])
        : "r"(a[0]), "r"(a[1]), "r"(a[2]), "r"(a[3]), "r"(b0), "r"(b1));
}
__device__ __forceinline__ void cp16u(unsigned* dst, const unsigned* src) {
    unsigned sa = (unsigned)__cvta_generic_to_shared(dst);
    asm volatile("cp.async.cg.shared.global [%0], [%1], 16;" :: "r"(sa), "l"(src));
}
__device__ __forceinline__ void ldmx4(unsigned* r, unsigned saddr) {
    asm volatile("ldmatrix.sync.aligned.m8n8.x4.shared.b16 {%0,%1,%2,%3}, [%4];"
                 : "=r"(r[0]), "=r"(r[1]), "=r"(r[2]), "=r"(r[3]) : "r"(saddr));
}

// ---------------- init + W conversion (3 launches before gemm) -------------
__global__ void init_n1a_kernel() {
    int i = blockIdx.x * blockDim.x + threadIdx.x;
    if (i < NN * 8) ((float4*)g_numer1)[i] = make_float4(0.f, 0.f, 0.f, 0.f);
}
__global__ void init_n1b_kernel() {
    int i = blockIdx.x * blockDim.x + threadIdx.x;
    if (i < NN * 8) ((float4*)g_numer1)[NN * 8 + i] = make_float4(0.f, 0.f, 0.f, 0.f);
}
// W [KF,64] f32 -> [n][kp] packed bf16x2 hi/lo, zero-padded to KP_TOT
__global__ void convw_kernel(const float* __restrict__ W) {
    int i = blockIdx.x * blockDim.x + threadIdx.x;
    if (i >= 64 * KP_TOT) return;
    int n = i / KP_TOT;
    int kp = i - n * KP_TOT;
    int k0 = 2 * kp, k1 = k0 + 1;
    float f0 = (k0 < KF) ? W[(size_t)k0 * 64 + n] : 0.f;
    float f1 = (k1 < KF) ? W[(size_t)k1 * 64 + n] : 0.f;
    unsigned hi = pk_bf(f0, f1);
    unsigned lo = pk_bf(f0 - bf_lo(hi), f1 - bf_hi(hi));
    g_Whi[i] = hi;
    g_Wlo[i] = lo;
}
__global__ void init_d_kernel() {
    int i = blockIdx.x * blockDim.x + threadIdx.x;
    if (i < NN * 2) ((float4*)g_denom1)[i] = make_float4(0.f, 0.f, 0.f, 0.f);
}

// ---------------- K1: feat1 = features @ W1 (3xBF16, ldmatrix B) -----------
__global__ __launch_bounds__(256) void gemm1_kernel(
    const float* __restrict__ A, const float* __restrict__ al,
    const float* __restrict__ ar) {
    extern __shared__ unsigned smem[];
    unsigned* sAhi = smem;                       // [2][SA_U32]
    unsigned* sAlo = smem + 2 * SA_U32;          // [2][SA_U32]
    unsigned* sB   = smem + 4 * SA_U32;          // buf0hi, buf0lo, buf1hi, buf1lo
    const unsigned sb_byte0 = (unsigned)__cvta_generic_to_shared(sB);

    const int bm   = blockIdx.x * BM;
    const int tid  = threadIdx.x;
    const int wid  = tid >> 5;
    const int lane = tid & 31;
    const int g    = lane >> 2;
    const int cq   = lane & 3;

    float acc[8][4];
#pragma unroll
    for (int n = 0; n < 8; n++)
#pragma unroll
        for (int i = 0; i < 4; i++) acc[n][i] = 0.f;

    // A staging registers: 8 pairs (16 floats) per thread per tile
    float rf[16];

    // thread -> (row, pair) mapping: i = tid + 256j, r = i>>4, kp = i&15
    auto ldgA = [&](int t) {
        const int k0 = t * BK;
        const bool full = (k0 + BK <= KF);
#pragma unroll
        for (int j = 0; j < 8; j++) {
            int i = tid + j * 256;
            int r = i >> 4, kp = i & 15;
            int row = bm + r;
            int c0 = k0 + 2 * kp;
            const float* p = A + (size_t)row * KF + c0;
            if (row < NN && full) {
                rf[2 * j]     = p[0];
                rf[2 * j + 1] = p[1];
            } else {
                rf[2 * j]     = (row < NN && c0 < KF)     ? p[0] : 0.f;
                rf[2 * j + 1] = (row < NN && c0 + 1 < KF) ? p[1] : 0.f;
            }
        }
    };
    auto cvtStoreA = [&](int buf) {
        unsigned* dh = sAhi + buf * SA_U32;
        unsigned* dl = sAlo + buf * SA_U32;
#pragma unroll
        for (int j = 0; j < 8; j++) {
            int i = tid + j * 256;
            int r = i >> 4, kp = i & 15;
            float f0 = rf[2 * j], f1 = rf[2 * j + 1];
            unsigned hi = pk_bf(f0, f1);
            unsigned lo = pk_bf(f0 - bf_lo(hi), f1 - bf_hi(hi));
            dh[r * ASTRIDE + kp] = hi;
            dl[r * ASTRIDE + kp] = lo;
        }
    };
    // B tile: [n][kp] rows of 16 u32 (+4 pad); one 16B cp.async per part per thread
    auto ldB = [&](int t, int buf) {
        int n = tid >> 2, kc = tid & 3;
        cp16u(sB + (2 * buf) * SB_U32 + n * BSTR + kc * 4,
              g_Whi + (size_t)n * KP_TOT + t * 16 + kc * 4);
        cp16u(sB + (2 * buf + 1) * SB_U32 + n * BSTR + kc * 4,
              g_Wlo + (size_t)n * KP_TOT + t * 16 + kc * 4);
        asm volatile("cp.async.commit_group;" ::: "memory");
    };

    // prologue
    ldgA(0);
    ldB(0, 0);
    cvtStoreA(0);
    asm volatile("cp.async.wait_group 0;" ::: "memory");
    __syncthreads();

    const int r0off = (wid * 16 + g) * ASTRIDE;

    for (int t = 0; t < NT_K; t++) {
        const int buf = t & 1;
        if (t + 1 < NT_K) {
            ldB(t + 1, buf ^ 1);
            ldgA(t + 1);
        }
        // ---- mma over tile t ----
        const unsigned* Ah = sAhi + buf * SA_U32;
        const unsigned* Al = sAlo + buf * SA_U32;
        const unsigned bhB = sb_byte0 + (2 * buf) * B_BYTES;
        const unsigned blB = bhB + B_BYTES;
#pragma unroll
        for (int s = 0; s < 2; s++) {              // two k16 steps per BK=32
            const int kp0 = s * 8;
            unsigned ahi[4], alo_[4];
            ahi[0]  = Ah[r0off + kp0 + cq];
            ahi[1]  = Ah[r0off + 8 * ASTRIDE + kp0 + cq];
            ahi[2]  = Ah[r0off + kp0 + 4 + cq];
            ahi[3]  = Ah[r0off + 8 * ASTRIDE + kp0 + 4 + cq];
            alo_[0] = Al[r0off + kp0 + cq];
            alo_[1] = Al[r0off + 8 * ASTRIDE + kp0 + cq];
            alo_[2] = Al[r0off + kp0 + 4 + cq];
            alo_[3] = Al[r0off + 8 * ASTRIDE + kp0 + 4 + cq];
            // B fragments via ldmatrix (verified mapping from R10):
            // lane -> n-row address; q0/q1 = b0 (kp0+cq) for nt0-3 / nt4-7,
            // q2/q3 = b1 (kp0+4+cq)
            const unsigned lb = (unsigned)(lane * 80 + 32 * s);
            unsigned q0[4], q1[4], q2[4], q3[4];
            ldmx4(q0, bhB + lb);
            ldmx4(q1, bhB + 2560 + lb);
            ldmx4(q2, bhB + lb + 16);
            ldmx4(q3, bhB + 2560 + lb + 16);
#pragma unroll
            for (int nt = 0; nt < 8; nt++) {
                unsigned b0 = (nt < 4) ? q0[nt] : q1[nt - 4];
                unsigned b1 = (nt < 4) ? q2[nt] : q3[nt - 4];
                mma_bf16(acc[nt], ahi, b0, b1);
                mma_bf16(acc[nt], alo_, b0, b1);
            }
            ldmx4(q0, blB + lb);
            ldmx4(q1, blB + 2560 + lb);
            ldmx4(q2, blB + lb + 16);
            ldmx4(q3, blB + 2560 + lb + 16);
#pragma unroll
            for (int nt = 0; nt < 8; nt++) {
                unsigned b0 = (nt < 4) ? q0[nt] : q1[nt - 4];
                unsigned b1 = (nt < 4) ? q2[nt] : q3[nt - 4];
                mma_bf16(acc[nt], ahi, b0, b1);
            }
        }
        if (t + 1 < NT_K) {
            cvtStoreA(buf ^ 1);
            asm volatile("cp.async.wait_group 0;" ::: "memory");
            __syncthreads();
        }
    }

    // ---- epilogue: store feat1 + fused el/er ----
    const int r0 = bm + wid * 16 + g;
    const int r1 = r0 + 8;
#pragma unroll
    for (int nt = 0; nt < 8; nt++) {
        float c0 = acc[nt][0], c1 = acc[nt][1], c2 = acc[nt][2], c3 = acc[nt][3];
        if (r0 < NN) *(float2*)&g_feat1[r0 * 64 + nt * 8 + 2 * cq] = make_float2(c0, c1);
        if (r1 < NN) *(float2*)&g_feat1[r1 * 64 + nt * 8 + 2 * cq] = make_float2(c2, c3);
        float al0 = __ldg(&al[nt * 8 + 2 * cq]), al1 = __ldg(&al[nt * 8 + 2 * cq + 1]);
        float ar0 = __ldg(&ar[nt * 8 + 2 * cq]), ar1 = __ldg(&ar[nt * 8 + 2 * cq + 1]);
        float el0 = c0 * al0 + c1 * al1, er0 = c0 * ar0 + c1 * ar1;
        float el1 = c2 * al0 + c3 * al1, er1 = c2 * ar0 + c3 * ar1;
#pragma unroll
        for (int m = 1; m < 4; m <<= 1) {
            el0 += __shfl_xor_sync(0xffffffff, el0, m);
            er0 += __shfl_xor_sync(0xffffffff, er0, m);
            el1 += __shfl_xor_sync(0xffffffff, el1, m);
            er1 += __shfl_xor_sync(0xffffffff, er1, m);
        }
        if (cq == 0) {
            if (r0 < NN) { g_el1[r0 * 8 + nt] = el0; g_er1[r0 * 8 + nt] = er0; }
            if (r1 < NN) { g_el1[r1 * 8 + nt] = el1; g_er1[r1 * 8 + nt] = er1; }
        }
    }
}

// ---------------- K2: layer-1 edge pass ------------------------------------
__global__ void edge1_kernel(const int* __restrict__ src, const int* __restrict__ dst) {
    int t = blockIdx.x * blockDim.x + threadIdx.x;
    int e = t >> 3;
    if (e >= NE) return;
    int h = t & 7;
    int s = __ldg(&src[e]);
    int d = __ldg(&dst[e]);
    float x = g_el1[s * 8 + h] + g_er1[d * 8 + h];
    float ex = __expf(lrelu(x));
    atomicAdd(&g_denom1[d * 8 + h], ex);
    const float4* f = (const float4*)&g_feat1[s * 64 + h * 8];
    float4 a = f[0], b = f[1];
    red_add_v4(&g_numer1[d * 64 + h * 8],     ex * a.x, ex * a.y, ex * a.z, ex * a.w);
    red_add_v4(&g_numer1[d * 64 + h * 8 + 4], ex * b.x, ex * b.y, ex * b.z, ex * b.w);
}

// ---------------- K3: finalize layer1 + MHI pooling + layer2 features ------
__global__ __launch_bounds__(256) void node_kernel(
    const float* __restrict__ b1, const float* __restrict__ Wm,
    const float* __restrict__ bm, const float* __restrict__ a,
    const float* __restrict__ W2, const float* __restrict__ al2,
    const float* __restrict__ ar2) {
    int n = blockIdx.x * blockDim.x + threadIdx.x;
    if (n >= NN) return;

    float x[8][8];
#pragma unroll
    for (int h = 0; h < 8; h++) {
        float dn  = g_denom1[n * 8 + h];
        float inv = dn > 0.f ? 1.f / dn : 0.f;
#pragma unroll
        for (int o = 0; o < 8; o++) {
            float v = g_numer1[n * 64 + h * 8 + o] * inv + __ldg(&b1[h * 8 + o]);
            x[h][o] = v > 0.f ? v : 0.f;
        }
    }
    float xm[8], eh[8];
#pragma unroll
    for (int i = 0; i < 8; i++) xm[i] = 0.f;
#pragma unroll
    for (int h = 0; h < 8; h++) {
        float s = 0.f;
#pragma unroll
        for (int i = 0; i < 8; i++) {
            float xl = __ldg(&bm[i]);
#pragma unroll
            for (int j = 0; j < 8; j++) xl += x[h][j] * __ldg(&Wm[i * 8 + j]);
            xm[i] += xl;
            s += xl * __ldg(&a[i]);
        }
        eh[h] = s;
    }
    float ebar = 0.f;
#pragma unroll
    for (int i = 0; i < 8; i++) ebar += (xm[i] * 0.125f) * __ldg(&a[8 + i]);
    float ssum = 0.f;
#pragma unroll
    for (int h = 0; h < 8; h++) {
        float v = eh[h] + ebar;
        v = v > 0.f ? v : 0.f;
        v = __expf(v);
        eh[h] = v;
        ssum += v;
    }
    float rs = 1.f / ssum;
    float hv[8];
#pragma unroll
    for (int m = 0; m < 8; m++) {
        float s = 0.f;
#pragma unroll
        for (int h = 0; h < 8; h++) s += x[h][m] * eh[h];
        hv[m] = s * rs;
    }
    float f2[8];
#pragma unroll
    for (int o = 0; o < 7; o++) {
        float s = 0.f;
#pragma unroll
        for (int m = 0; m < 8; m++) s += hv[m] * __ldg(&W2[m * 7 + o]);
        f2[o] = s;
    }
    f2[7] = 1.f;
    float el = 0.f, er = 0.f;
#pragma unroll
    for (int o = 0; o < 7; o++) {
        el += f2[o] * __ldg(&al2[o]);
        er += f2[o] * __ldg(&ar2[o]);
    }
    float4* out4 = (float4*)&g_feat2p[n * 8];
    out4[0] = make_float4(f2[0], f2[1], f2[2], f2[3]);
    out4[1] = make_float4(f2[4], f2[5], f2[6], f2[7]);
    g_el2[n] = el;
    g_er2[n] = er;
    float4* acc = (float4*)&g_acc2[n * 8];
    acc[0] = make_float4(0.f, 0.f, 0.f, 0.f);
    acc[1] = make_float4(0.f, 0.f, 0.f, 0.f);
}

// ---------------- K4: layer-2 edge pass ------------------------------------
__global__ void edge2_kernel(const int* __restrict__ src, const int* __restrict__ dst) {
    int e = blockIdx.x * blockDim.x + threadIdx.x;
    if (e >= NE) return;
    int s = __ldg(&src[e]);
    int d = __ldg(&dst[e]);
    float xx = g_el2[s] + g_er2[d];
    float ex = __expf(lrelu(xx));
    const float4* f = (const float4*)&g_feat2p[s * 8];
    float4 a = f[0], b = f[1];
    red_add_v4(&g_acc2[d * 8],     ex * a.x, ex * a.y, ex * a.z, ex * a.w);
    red_add_v4(&g_acc2[d * 8 + 4], ex * b.x, ex * b.y, ex * b.z, ex * b.w);
}

// ---------------- K5: final output -----------------------------------------
__global__ void final_kernel(const float* __restrict__ b2, float* __restrict__ out) {
    int t = blockIdx.x * blockDim.x + threadIdx.x;
    if (t >= NN * 7) return;
    int n = t / 7, o = t - n * 7;
    float dn = g_acc2[n * 8 + 7];
    float v  = dn > 0.f ? g_acc2[n * 8 + o] / dn : 0.f;
    out[t] = v + __ldg(&b2[o]);
}

// ---------------- launch ----------------------------------------------------
extern "C" void kernel_launch(void* const* d_in, const int* in_sizes, int n_in,
                              void* d_out, int out_size) {
    const float* features = (const float*)d_in[0];
    const int*   src      = (const int*)d_in[1];
    const int*   dst      = (const int*)d_in[2];
    const float* W1       = (const float*)d_in[3];
    const float* attn_l1  = (const float*)d_in[4];
    const float* attn_r1  = (const float*)d_in[5];
    const float* b1       = (const float*)d_in[6];
    const float* Wm       = (const float*)d_in[7];
    const float* bm       = (const float*)d_in[8];
    const float* a        = (const float*)d_in[9];
    const float* W2       = (const float*)d_in[10];
    const float* attn_l2  = (const float*)d_in[11];
    const float* attn_r2  = (const float*)d_in[12];
    const float* b2       = (const float*)d_in[13];
    float* out = (float*)d_out;

    (void)cudaFuncSetAttribute(gemm1_kernel,
                               cudaFuncAttributeMaxDynamicSharedMemorySize, SMEM_BYTES);

    // 3 launches before gemm1 so it remains the profiled (4th) node
    init_n1a_kernel<<<(NN * 8 + 255) / 256, 256>>>();
    init_n1b_kernel<<<(NN * 8 + 255) / 256, 256>>>();
    convw_kernel<<<(64 * KP_TOT + 255) / 256, 256>>>(W1);
    gemm1_kernel<<<(NN + BM - 1) / BM, 256, SMEM_BYTES>>>(features, attn_l1, attn_r1);
    init_d_kernel<<<(NN * 2 + 255) / 256, 256>>>();
    edge1_kernel<<<(NE * 8 + 255) / 256, 256>>>(src, dst);
    node_kernel<<<(NN + 255) / 256, 256>>>(b1, Wm, bm, a, W2, attn_l2, attn_r2);
    edge2_kernel<<<(NE + 255) / 256, 256>>>(src, dst);
    final_kernel<<<(NN * 7 + 255) / 256, 256>>>(b2, out);
}